// round 3
// baseline (speedup 1.0000x reference)
#include <cuda_runtime.h>
#include <cuda_fp16.h>
#include <cstdint>
#include <cstddef>

#define NN 8192
#define EMBD 256
#define NHID 64
#define ALPHA 0.2f

#define MROWS 128
#define KC 64
#define NB 72
#define JSPLIT 2
#define JHALF (NN / JSPLIT)
#define NCHUNK (JHALF / KC)   // 64

// smem layout (k_attn)
#define T_OFF 0
#define S_OFF 16384
#define ADJ_OFF 16896
#define ADJ_STAGE 32768
#define B_OFF (ADJ_OFF + 2 * ADJ_STAGE)      // 82432
#define B_STAGE 18432                         // 2 mats x 72 rows x 128B
#define SMEM3_TOTAL (B_OFF + 2 * B_STAGE)     // 119296

// ---------------- device scratch ----------------
__device__ float g_h[NN * NHID];
__device__ float g_s[NN], g_t[NN];
__device__ float g_a[NN], g_b[NN];
__device__ __half g_B[2 * NB * NN];           // [mat][c][j], j contiguous (BT layout)
__device__ float g_part[JSPLIT * NN * NB];    // numer cols 0..63, denom col 64

// ---------------- helpers ----------------
__device__ __forceinline__ uint32_t smem_u32(const void* p) {
    uint32_t a;
    asm("{ .reg .u64 t; cvta.to.shared.u64 t, %1; cvt.u32.u64 %0, t; }" : "=r"(a) : "l"(p));
    return a;
}
__device__ __forceinline__ void cp_async16(uint32_t dst, const void* src) {
    asm volatile("cp.async.cg.shared.global [%0], [%1], 16;" :: "r"(dst), "l"(src));
}
__device__ __forceinline__ void ldsm4(uint32_t& r0, uint32_t& r1, uint32_t& r2, uint32_t& r3, uint32_t a) {
    asm volatile("ldmatrix.sync.aligned.m8n8.x4.shared.b16 {%0,%1,%2,%3}, [%4];"
                 : "=r"(r0), "=r"(r1), "=r"(r2), "=r"(r3) : "r"(a));
}
__device__ __forceinline__ void ldsm2(uint32_t& r0, uint32_t& r1, uint32_t a) {
    asm volatile("ldmatrix.sync.aligned.m8n8.x2.shared.b16 {%0,%1}, [%2];"
                 : "=r"(r0), "=r"(r1) : "r"(a));
}
__device__ __forceinline__ void mma16816(float* d, const uint32_t* a, uint32_t b0, uint32_t b1) {
    asm volatile("mma.sync.aligned.m16n8k16.row.col.f32.f16.f16.f32 "
                 "{%0,%1,%2,%3}, {%4,%5,%6,%7}, {%8,%9}, {%0,%1,%2,%3};"
                 : "+f"(d[0]), "+f"(d[1]), "+f"(d[2]), "+f"(d[3])
                 : "r"(a[0]), "r"(a[1]), "r"(a[2]), "r"(a[3]), "r"(b0), "r"(b1));
}
__device__ __forceinline__ void mkfrag(int wx, int wy, float s, float tx, float ty,
                                       uint32_t& f1, uint32_t& f2) {
    bool m0 = wx > 0, m1 = wy > 0;
    bool c0 = (s + tx) >= 0.f, c1 = (s + ty) >= 0.f;
    f1 = ((m0 && c0) ? 0x3C00u : 0u) | ((m1 && c1) ? 0x3C000000u : 0u);
    f2 = ((m0 && !c0) ? 0x3C00u : 0u) | ((m1 && !c1) ? 0x3C000000u : 0u);
}

// ================= Kernel 1: h = input @ W (fp32 CUDA cores) =================
__global__ void __launch_bounds__(256) k_gemm_h(const float* __restrict__ inp, const float* __restrict__ W) {
    int row = blockIdx.x * 32 + (threadIdx.x >> 3);
    int c0 = (threadIdx.x & 7) * 8;
    float acc[8];
#pragma unroll
    for (int i = 0; i < 8; i++) acc[i] = 0.f;
    const float* ir = inp + (size_t)row * EMBD;
    for (int k0 = 0; k0 < EMBD; k0 += 4) {
        float4 x = __ldg(reinterpret_cast<const float4*>(ir + k0));
#pragma unroll
        for (int kk = 0; kk < 4; kk++) {
            float xv = (&x.x)[kk];
            const float* wr = W + (k0 + kk) * NHID + c0;
            float4 w0 = __ldg(reinterpret_cast<const float4*>(wr));
            float4 w1 = __ldg(reinterpret_cast<const float4*>(wr + 4));
            acc[0] += xv * w0.x; acc[1] += xv * w0.y; acc[2] += xv * w0.z; acc[3] += xv * w0.w;
            acc[4] += xv * w1.x; acc[5] += xv * w1.y; acc[6] += xv * w1.z; acc[7] += xv * w1.w;
        }
    }
    float* hp = g_h + (size_t)row * NHID + c0;
    *reinterpret_cast<float4*>(hp) = make_float4(acc[0], acc[1], acc[2], acc[3]);
    *reinterpret_cast<float4*>(hp + 4) = make_float4(acc[4], acc[5], acc[6], acc[7]);
}

// ================= Kernel 2: per-node scalars + fp16 B operands =================
__global__ void __launch_bounds__(256) k_prep(const float* __restrict__ av) {
    int j = blockIdx.x * 256 + threadIdx.x;
    float hrow[64];
#pragma unroll
    for (int q = 0; q < 16; q++) {
        float4 v = *reinterpret_cast<const float4*>(g_h + (size_t)j * NHID + q * 4);
        hrow[q * 4] = v.x; hrow[q * 4 + 1] = v.y; hrow[q * 4 + 2] = v.z; hrow[q * 4 + 3] = v.w;
    }
    float s = 0.f, t = 0.f;
#pragma unroll
    for (int c = 0; c < 64; c++) {
        s += hrow[c] * __ldg(av + c);
        t += hrow[c] * __ldg(av + 64 + c);
    }
    g_s[j] = s;
    g_t[j] = t;
    g_a[j] = expf(s);
    g_b[j] = expf(ALPHA * s);
    float u = expf(t), v = expf(ALPHA * t);

#pragma unroll
    for (int c = 0; c < 64; c++) {
        g_B[((size_t)0 * NB + c) * NN + j] = __float2half(u * hrow[c]);
        g_B[((size_t)1 * NB + c) * NN + j] = __float2half(v * hrow[c]);
    }
    g_B[((size_t)0 * NB + 64) * NN + j] = __float2half(u);   // denom column
    g_B[((size_t)1 * NB + 64) * NN + j] = __float2half(v);
#pragma unroll
    for (int c = 65; c < NB; c++) {
        g_B[((size_t)0 * NB + c) * NN + j] = __half(0.f);
        g_B[((size_t)1 * NB + c) * NN + j] = __half(0.f);
    }
}

// ================= Kernel 3: masked dual GEMM via mma.sync =================
__device__ __forceinline__ void issue_chunk(uint32_t sb, const int* __restrict__ adj,
                                            int I0, int jb, int s, int tid) {
    const uint32_t adjst = sb + ADJ_OFF + s * ADJ_STAGE;
#pragma unroll
    for (int it = 0; it < 8; it++) {
        int u = tid + it * 256;
        int row = u >> 4, ku = u & 15;
        const void* src = adj + (size_t)(I0 + row) * NN + jb + ku * 4;
        uint32_t dst = adjst + (uint32_t)(row * 256 + ((ku * 16) ^ ((row & 7) << 4)));
        cp_async16(dst, src);
    }
    const uint32_t bst = sb + B_OFF + s * B_STAGE;
#pragma unroll
    for (int it = 0; it < 5; it++) {
        int v = tid + it * 256;
        if (v < 1152) {
            int m = v / 576;
            int rem = v - m * 576;
            int c = rem >> 3, seg = rem & 7;
            const void* src = g_B + ((size_t)m * NB + c) * NN + jb + seg * 8;
            uint32_t dst = bst + m * 9216 + (uint32_t)(c * 128 + ((seg * 16) ^ ((c & 7) << 4)));
            cp_async16(dst, src);
        }
    }
    asm volatile("cp.async.commit_group;" ::: "memory");
}

__global__ void __launch_bounds__(256, 1) k_attn(const int* __restrict__ adj) {
    extern __shared__ char smem[];
    const uint32_t sb = smem_u32(smem);
    float* t_sh = reinterpret_cast<float*>(smem + T_OFF);
    float* s_sh = reinterpret_cast<float*>(smem + S_OFF);

    const int tid = threadIdx.x;
    const int wid = tid >> 5, lane = tid & 31;
    const int r = lane >> 2, cL = lane & 3;
    const int rloc = wid * 16 + r;
    const int I0 = blockIdx.x * MROWS;
    const int jh = blockIdx.y;
    const int jbase0 = jh * JHALF;

    // prologue: start streaming chunks 0,1
    issue_chunk(sb, adj, I0, jbase0, 0, tid);
    issue_chunk(sb, adj, I0, jbase0 + KC, 1, tid);

    // t for the whole j-half + s for the row block
    {
        const float4* tsrc = reinterpret_cast<const float4*>(g_t + jbase0);
        float4* tdst = reinterpret_cast<float4*>(t_sh);
#pragma unroll 4
        for (int i = tid; i < JHALF / 4; i += 256) tdst[i] = tsrc[i];
        if (tid < MROWS) s_sh[tid] = g_s[I0 + tid];
    }

    // per-lane geometry
    const uint32_t swzA = (uint32_t)(r << 4);
    const uint32_t swzB = (uint32_t)((lane & 7) << 4);
    const uint32_t kaddB = (uint32_t)(((lane >> 3) & 1) * 16);
    uint32_t rb[5];
#pragma unroll
    for (int g = 0; g < 4; g++)
        rb[g] = (uint32_t)(((2 * g + ((lane >> 4) & 1)) * 8 + (lane & 7)) * 128);
    rb[4] = (uint32_t)((64 + (lane & 7)) * 128);

    float acc1[9][4], acc2[9][4];
#pragma unroll
    for (int nt = 0; nt < 9; nt++)
#pragma unroll
        for (int k = 0; k < 4; k++) { acc1[nt][k] = 0.f; acc2[nt][k] = 0.f; }

    float s0 = 0.f, s1 = 0.f;

    for (int q = 0; q < NCHUNK; q++) {
        const int s = q & 1;
        if (q < NCHUNK - 1) asm volatile("cp.async.wait_group 1;" ::: "memory");
        else                asm volatile("cp.async.wait_group 0;" ::: "memory");
        __syncthreads();
        if (q == 0) { s0 = s_sh[rloc]; s1 = s_sh[rloc + 8]; }

        const char* adjp = smem + ADJ_OFF + s * ADJ_STAGE;
        const uint32_t bstU = sb + B_OFF + s * B_STAGE;
        const uint32_t bstV = bstU + 9216;
        const float* tq = t_sh + q * KC;

#pragma unroll
        for (int ksi = 0; ksi < 4; ksi++) {
            const int ks = ksi * 16;
            float2 tA = *reinterpret_cast<const float2*>(tq + ks + 2 * cL);
            float2 tB = *reinterpret_cast<const float2*>(tq + ks + 8 + 2 * cL);
            uint32_t ka = (uint32_t)(ks * 4 + cL * 8);
            int2 w00 = *reinterpret_cast<const int2*>(adjp + rloc * 256 + (ka ^ swzA));
            int2 w10 = *reinterpret_cast<const int2*>(adjp + (rloc + 8) * 256 + (ka ^ swzA));
            int2 w01 = *reinterpret_cast<const int2*>(adjp + rloc * 256 + ((ka + 32) ^ swzA));
            int2 w11 = *reinterpret_cast<const int2*>(adjp + (rloc + 8) * 256 + ((ka + 32) ^ swzA));

            uint32_t A1[4], A2[4];
            mkfrag(w00.x, w00.y, s0, tA.x, tA.y, A1[0], A2[0]);
            mkfrag(w10.x, w10.y, s1, tA.x, tA.y, A1[1], A2[1]);
            mkfrag(w01.x, w01.y, s0, tB.x, tB.y, A1[2], A2[2]);
            mkfrag(w11.x, w11.y, s1, tB.x, tB.y, A1[3], A2[3]);

            const uint32_t inner = ((uint32_t)(ks * 2) + kaddB) ^ swzB;
#pragma unroll
            for (int g = 0; g < 4; g++) {
                uint32_t u0, u1, u2, u3;
                ldsm4(u0, u1, u2, u3, bstU + rb[g] + inner);
                mma16816(acc1[2 * g], A1, u0, u1);
                mma16816(acc1[2 * g + 1], A1, u2, u3);
                uint32_t v0, v1, v2, v3;
                ldsm4(v0, v1, v2, v3, bstV + rb[g] + inner);
                mma16816(acc2[2 * g], A2, v0, v1);
                mma16816(acc2[2 * g + 1], A2, v2, v3);
            }
            {
                uint32_t u0, u1, v0, v1;
                ldsm2(u0, u1, bstU + rb[4] + inner);
                mma16816(acc1[8], A1, u0, u1);
                ldsm2(v0, v1, bstV + rb[4] + inner);
                mma16816(acc2[8], A2, v0, v1);
            }
        }
        __syncthreads();
        if (q + 2 < NCHUNK)
            issue_chunk(sb, adj, I0, jbase0 + (q + 2) * KC, s, tid);
    }

    // epilogue: numer = a_i * acc1 + b_i * acc2  (col 64 = denom partial)
    const int i0 = I0 + rloc, i1 = i0 + 8;
    const float af0 = g_a[i0], bf0 = g_b[i0];
    const float af1 = g_a[i1], bf1 = g_b[i1];
    float* p0 = g_part + ((size_t)jh * NN + i0) * NB;
    float* p1 = g_part + ((size_t)jh * NN + i1) * NB;
#pragma unroll
    for (int nt = 0; nt < 9; nt++) {
        const int n = nt * 8 + 2 * cL;
        float2 x0 = make_float2(af0 * acc1[nt][0] + bf0 * acc2[nt][0],
                                af0 * acc1[nt][1] + bf0 * acc2[nt][1]);
        float2 x1 = make_float2(af1 * acc1[nt][2] + bf1 * acc2[nt][2],
                                af1 * acc1[nt][3] + bf1 * acc2[nt][3]);
        *reinterpret_cast<float2*>(p0 + n) = x0;
        *reinterpret_cast<float2*>(p1 + n) = x1;
    }
}

// ================= Kernel 4: combine halves, divide =================
__global__ void __launch_bounds__(256) k_combine(float* __restrict__ out) {
    int idx = blockIdx.x * 256 + threadIdx.x;
    int i = idx >> 6, c = idx & 63;
    const float* p0 = g_part + (size_t)i * NB;
    const float* p1 = g_part + (size_t)(NN + i) * NB;
    float den = p0[64] + p1[64];
    out[idx] = (p0[c] + p1[c]) / den;
}

// ================= launcher =================
extern "C" void kernel_launch(void* const* d_in, const int* in_sizes, int n_in,
                              void* d_out, int out_size) {
    const float* inp = (const float*)d_in[0];
    const int* adj   = (const int*)d_in[1];
    const float* W   = (const float*)d_in[2];
    const float* av  = (const float*)d_in[3];
    float* out = (float*)d_out;
    (void)in_sizes; (void)n_in; (void)out_size;

    cudaFuncSetAttribute(k_attn, cudaFuncAttributeMaxDynamicSharedMemorySize, SMEM3_TOTAL);

    k_gemm_h<<<NN / 32, 256>>>(inp, W);
    k_prep<<<NN / 256, 256>>>(av);
    dim3 g3(NN / MROWS, JSPLIT);
    k_attn<<<g3, 256, SMEM3_TOTAL>>>(adj);
    k_combine<<<(NN * NHID) / 256, 256>>>(out);
}

// round 4
// speedup vs baseline: 1.4717x; 1.4717x over previous
#include <cuda_runtime.h>
#include <cuda_fp16.h>
#include <cstdint>
#include <cstddef>

#define NN 8192
#define EMBD 256
#define NHID 64
#define ALPHA 0.2f

#define MROWS 128
#define KC 64
#define NB 72
#define JSPLIT 2
#define JHALF (NN / JSPLIT)
#define NCHUNK (JHALF / KC)   // 64

// smem layout (k_attn): u/v tables then 4 pipeline stages
#define U_OFF 0
#define V_OFF 8192
#define STAGE0 16384
#define ADJ_SZ 32768                       // 128 rows x 256B
#define B_SZ 9216                          // 72 rows x 128B
#define STAGE_SZ (ADJ_SZ + B_SZ)           // 41984
#define NSTAGE 4
#define SMEM3_TOTAL (STAGE0 + NSTAGE * STAGE_SZ)   // 184320

// ---------------- device scratch ----------------
__device__ __half g_Bm[NB * NN];            // [c][j]: h cols (c<64), ones (64), pad 0
__device__ __half g_u[NN], g_v[NN];         // exp(t_j), exp(a*t_j)
__device__ float g_af[NN], g_bf[NN], g_iv[NN];  // exp(s), exp(a*s), exp(-s)
__device__ float g_part[JSPLIT * NN * NB];  // numer 0..63, denom 64

// ---------------- helpers ----------------
__device__ __forceinline__ uint32_t smem_u32(const void* p) {
    uint32_t a;
    asm("{ .reg .u64 t; cvta.to.shared.u64 t, %1; cvt.u32.u64 %0, t; }" : "=r"(a) : "l"(p));
    return a;
}
__device__ __forceinline__ void cp_async16(uint32_t dst, const void* src) {
    asm volatile("cp.async.cg.shared.global [%0], [%1], 16;" :: "r"(dst), "l"(src));
}
__device__ __forceinline__ void ldsm4(uint32_t& r0, uint32_t& r1, uint32_t& r2, uint32_t& r3, uint32_t a) {
    asm volatile("ldmatrix.sync.aligned.m8n8.x4.shared.b16 {%0,%1,%2,%3}, [%4];"
                 : "=r"(r0), "=r"(r1), "=r"(r2), "=r"(r3) : "r"(a));
}
__device__ __forceinline__ void ldsm2(uint32_t& r0, uint32_t& r1, uint32_t a) {
    asm volatile("ldmatrix.sync.aligned.m8n8.x2.shared.b16 {%0,%1}, [%2];"
                 : "=r"(r0), "=r"(r1) : "r"(a));
}
__device__ __forceinline__ void mma16816(float* d, const uint32_t* a, uint32_t b0, uint32_t b1) {
    asm volatile("mma.sync.aligned.m16n8k16.row.col.f32.f16.f16.f32 "
                 "{%0,%1,%2,%3}, {%4,%5,%6,%7}, {%8,%9}, {%0,%1,%2,%3};"
                 : "+f"(d[0]), "+f"(d[1]), "+f"(d[2]), "+f"(d[3])
                 : "r"(a[0]), "r"(a[1]), "r"(a[2]), "r"(a[3]), "r"(b0), "r"(b1));
}
// P pair for 2 j's: adj * (u>=inva ? a*u : b*v), packed f16x2
__device__ __forceinline__ uint32_t frag(int2 w, __half2 u2, __half2 v2,
                                         __half2 a2, __half2 b2, __half2 iv2) {
    __half2 sel = __hge2(u2, iv2);                  // 1.0 / 0.0 per half
    __half2 au = __hmul2(a2, u2);
    __half2 bv = __hmul2(b2, v2);
    __half2 val = __hfma2(sel, __hsub2(au, bv), bv);
    uint32_t m = (uint32_t)w.x * 0x3C00u + (uint32_t)w.y * 0x3C000000u;  // adj in {0,1}
    __half2 res = __hmul2(val, *reinterpret_cast<__half2*>(&m));
    return *reinterpret_cast<uint32_t*>(&res);
}

// ============ Kernel 1: h = input@W fused with all prep ============
__global__ void __launch_bounds__(256) k_prep(const float* __restrict__ inp,
                                              const float* __restrict__ W,
                                              const float* __restrict__ av) {
    int j = blockIdx.x * 32 + (threadIdx.x >> 3);
    int c0 = (threadIdx.x & 7) * 8;
    float acc[8];
#pragma unroll
    for (int i = 0; i < 8; i++) acc[i] = 0.f;
    const float* ir = inp + (size_t)j * EMBD;
    for (int k0 = 0; k0 < EMBD; k0 += 4) {
        float4 x = __ldg(reinterpret_cast<const float4*>(ir + k0));
#pragma unroll
        for (int kk = 0; kk < 4; kk++) {
            float xv = (&x.x)[kk];
            const float* wr = W + (k0 + kk) * NHID + c0;
            float4 w0 = __ldg(reinterpret_cast<const float4*>(wr));
            float4 w1 = __ldg(reinterpret_cast<const float4*>(wr + 4));
            acc[0] += xv * w0.x; acc[1] += xv * w0.y; acc[2] += xv * w0.z; acc[3] += xv * w0.w;
            acc[4] += xv * w1.x; acc[5] += xv * w1.y; acc[6] += xv * w1.z; acc[7] += xv * w1.w;
        }
    }
    // s,t via 8-lane reduction
    float s = 0.f, t = 0.f;
#pragma unroll
    for (int k = 0; k < 8; k++) {
        s += acc[k] * __ldg(av + c0 + k);
        t += acc[k] * __ldg(av + 64 + c0 + k);
    }
#pragma unroll
    for (int o = 1; o < 8; o <<= 1) {
        s += __shfl_xor_sync(0xFFFFFFFFu, s, o);
        t += __shfl_xor_sync(0xFFFFFFFFu, t, o);
    }
    // B matrix columns (transposed: [c][j])
#pragma unroll
    for (int k = 0; k < 8; k++)
        g_Bm[(size_t)(c0 + k) * NN + j] = __float2half(acc[k]);
    if ((threadIdx.x & 7) == 0) {
        g_u[j] = __float2half(expf(t));
        g_v[j] = __float2half(expf(ALPHA * t));
        g_af[j] = expf(s);
        g_bf[j] = expf(ALPHA * s);
        g_iv[j] = expf(-s);
        g_Bm[(size_t)64 * NN + j] = __float2half(1.f);
#pragma unroll
        for (int c = 65; c < NB; c++) g_Bm[(size_t)c * NN + j] = __half(0.f);
    }
}

// ============ Kernel 2: single masked GEMM via mma.sync ============
__device__ __forceinline__ void issue_chunk(uint32_t sb, const int* __restrict__ adj,
                                            int I0, int jb, int st, int tid) {
    const uint32_t stage = sb + STAGE0 + st * STAGE_SZ;
#pragma unroll
    for (int it = 0; it < 8; it++) {
        int u = tid + it * 256;
        int row = u >> 4, ku = u & 15;
        cp_async16(stage + (uint32_t)(row * 256 + ((ku * 16) ^ ((row & 7) << 4))),
                   adj + (size_t)(I0 + row) * NN + jb + ku * 4);
    }
    const uint32_t bst = stage + ADJ_SZ;
#pragma unroll
    for (int it = 0; it < 3; it++) {
        int v = tid + it * 256;
        if (v < 576) {
            int c = v >> 3, seg = v & 7;
            cp_async16(bst + (uint32_t)(c * 128 + ((seg * 16) ^ ((c & 7) << 4))),
                       g_Bm + (size_t)c * NN + jb + seg * 8);
        }
    }
    asm volatile("cp.async.commit_group;" ::: "memory");
}

__global__ void __launch_bounds__(256, 1) k_attn(const int* __restrict__ adj) {
    extern __shared__ char smem[];
    const uint32_t sb = smem_u32(smem);
    const int tid = threadIdx.x;
    const int wid = tid >> 5, lane = tid & 31;
    const int r = lane >> 2, cL = lane & 3;
    const int rloc = wid * 16 + r;
    const int I0 = blockIdx.x * MROWS;
    const int jh = blockIdx.y;
    const int jbase0 = jh * JHALF;

    issue_chunk(sb, adj, I0, jbase0, 0, tid);
    issue_chunk(sb, adj, I0, jbase0 + KC, 1, tid);

    // u/v tables for this j-half (8KB each)
    __half* u_sh = reinterpret_cast<__half*>(smem + U_OFF);
    __half* v_sh = reinterpret_cast<__half*>(smem + V_OFF);
#pragma unroll
    for (int i = tid; i < JHALF / 8; i += 256) {
        reinterpret_cast<float4*>(u_sh)[i] = reinterpret_cast<const float4*>(g_u + jbase0)[i];
        reinterpret_cast<float4*>(v_sh)[i] = reinterpret_cast<const float4*>(g_v + jbase0)[i];
    }

    // per-row scalars (2 rows per lane) as half2 broadcasts
    const int i0 = I0 + rloc, i1 = i0 + 8;
    const __half2 a20 = __float2half2_rn(g_af[i0]), b20 = __float2half2_rn(g_bf[i0]);
    const __half2 iv0 = __float2half2_rn(g_iv[i0]);
    const __half2 a21 = __float2half2_rn(g_af[i1]), b21 = __float2half2_rn(g_bf[i1]);
    const __half2 iv1 = __float2half2_rn(g_iv[i1]);

    // geometry
    const uint32_t swzA = (uint32_t)(r << 4);
    const uint32_t swzB = (uint32_t)((lane & 7) << 4);
    const uint32_t kaddB = (uint32_t)(((lane >> 3) & 1) * 16);
    uint32_t rb[5];
#pragma unroll
    for (int g = 0; g < 4; g++)
        rb[g] = (uint32_t)(((2 * g + ((lane >> 4) & 1)) * 8 + (lane & 7)) * 128);
    rb[4] = (uint32_t)((64 + (lane & 7)) * 128);

    float acc[9][4];
#pragma unroll
    for (int nt = 0; nt < 9; nt++)
#pragma unroll
        for (int k = 0; k < 4; k++) acc[nt][k] = 0.f;

    for (int q = 0; q < NCHUNK; q++) {
        if (q + 2 < NCHUNK)
            issue_chunk(sb, adj, I0, jbase0 + (q + 2) * KC, (q + 2) & 3, tid);
        if (q < NCHUNK - 2)      asm volatile("cp.async.wait_group 2;" ::: "memory");
        else if (q == NCHUNK - 2) asm volatile("cp.async.wait_group 1;" ::: "memory");
        else                      asm volatile("cp.async.wait_group 0;" ::: "memory");
        __syncthreads();   // single barrier per chunk: publishes stage q, frees stage q-1

        const char* adjp = smem + STAGE0 + (q & 3) * STAGE_SZ;
        const uint32_t bstB = sb + STAGE0 + (q & 3) * STAGE_SZ + ADJ_SZ;
        const __half* uq = u_sh + q * KC;
        const __half* vq = v_sh + q * KC;

#pragma unroll
        for (int ksi = 0; ksi < 4; ksi++) {
            const int ks = ksi * 16;
            __half2 u2lo = *reinterpret_cast<const __half2*>(uq + ks + 2 * cL);
            __half2 v2lo = *reinterpret_cast<const __half2*>(vq + ks + 2 * cL);
            __half2 u2hi = *reinterpret_cast<const __half2*>(uq + ks + 8 + 2 * cL);
            __half2 v2hi = *reinterpret_cast<const __half2*>(vq + ks + 8 + 2 * cL);
            uint32_t ka = (uint32_t)(ks * 4 + cL * 8);
            int2 w00 = *reinterpret_cast<const int2*>(adjp + rloc * 256 + (ka ^ swzA));
            int2 w10 = *reinterpret_cast<const int2*>(adjp + (rloc + 8) * 256 + (ka ^ swzA));
            int2 w01 = *reinterpret_cast<const int2*>(adjp + rloc * 256 + ((ka + 32) ^ swzA));
            int2 w11 = *reinterpret_cast<const int2*>(adjp + (rloc + 8) * 256 + ((ka + 32) ^ swzA));

            uint32_t A[4];
            A[0] = frag(w00, u2lo, v2lo, a20, b20, iv0);
            A[1] = frag(w10, u2lo, v2lo, a21, b21, iv1);
            A[2] = frag(w01, u2hi, v2hi, a20, b20, iv0);
            A[3] = frag(w11, u2hi, v2hi, a21, b21, iv1);

            const uint32_t inner = ((uint32_t)(ks * 2) + kaddB) ^ swzB;
#pragma unroll
            for (int g = 0; g < 4; g++) {
                uint32_t b0, b1, b2, b3;
                ldsm4(b0, b1, b2, b3, bstB + rb[g] + inner);
                mma16816(acc[2 * g], A, b0, b1);
                mma16816(acc[2 * g + 1], A, b2, b3);
            }
            {
                uint32_t b0, b1;
                ldsm2(b0, b1, bstB + rb[4] + inner);
                mma16816(acc[8], A, b0, b1);
            }
        }
    }

    // epilogue: raw partials (scaling already inside P)
    float* p0 = g_part + ((size_t)jh * NN + i0) * NB;
    float* p1 = g_part + ((size_t)jh * NN + i1) * NB;
#pragma unroll
    for (int nt = 0; nt < 9; nt++) {
        const int n = nt * 8 + 2 * cL;
        *reinterpret_cast<float2*>(p0 + n) = make_float2(acc[nt][0], acc[nt][1]);
        *reinterpret_cast<float2*>(p1 + n) = make_float2(acc[nt][2], acc[nt][3]);
    }
}

// ============ Kernel 3: combine halves, divide ============
__global__ void __launch_bounds__(256) k_combine(float* __restrict__ out) {
    int idx = blockIdx.x * 256 + threadIdx.x;
    int i = idx >> 6, c = idx & 63;
    const float* p0 = g_part + (size_t)i * NB;
    const float* p1 = g_part + (size_t)(NN + i) * NB;
    float den = p0[64] + p1[64];
    out[idx] = (p0[c] + p1[c]) / den;
}

// ============ launcher ============
extern "C" void kernel_launch(void* const* d_in, const int* in_sizes, int n_in,
                              void* d_out, int out_size) {
    const float* inp = (const float*)d_in[0];
    const int* adj   = (const int*)d_in[1];
    const float* W   = (const float*)d_in[2];
    const float* av  = (const float*)d_in[3];
    float* out = (float*)d_out;
    (void)in_sizes; (void)n_in; (void)out_size;

    cudaFuncSetAttribute(k_attn, cudaFuncAttributeMaxDynamicSharedMemorySize, SMEM3_TOTAL);

    k_prep<<<NN / 32, 256>>>(inp, W, av);
    dim3 g3(NN / MROWS, JSPLIT);
    k_attn<<<g3, 256, SMEM3_TOTAL>>>(adj);
    k_combine<<<(NN * NHID) / 256, 256>>>(out);
}

// round 5
// speedup vs baseline: 1.6436x; 1.1168x over previous
#include <cuda_runtime.h>
#include <cuda_fp16.h>
#include <cstdint>
#include <cstddef>

#define NN 8192
#define EMBD 256
#define NHID 64
#define ALPHA 0.2f

#define MROWS 128
#define KC 64
#define NB 72
#define JSPLIT 2
#define JHALF (NN / JSPLIT)
#define NCHUNK (JHALF / KC)   // 64

// smem layout (k_attn): u/v tables then 4 pipeline stages
#define U_OFF 0
#define V_OFF 8192
#define STAGE0 16384
#define ADJ_SZ 32768                       // 128 rows x 256B
#define B_SZ 9216                          // 72 rows x 128B
#define STAGE_SZ (ADJ_SZ + B_SZ)           // 41984
#define NSTAGE 4
#define SMEM3_TOTAL (STAGE0 + NSTAGE * STAGE_SZ)   // 184320

#define SMEM1_TOTAL (EMBD * NHID * 4)      // 64KB W staging

// ---------------- device scratch ----------------
__device__ __half g_Bm[NB * NN];            // [c][j]: h cols (c<64), ones (64), pad 0
__device__ __half g_u[NN], g_v[NN];         // exp(t_j), exp(a*t_j)
__device__ float g_af[NN], g_bf[NN], g_iv[NN];  // exp(s), exp(a*s), exp(-s)
__device__ float g_part[JSPLIT * NN * NB];  // numer 0..63, denom 64

// ---------------- helpers ----------------
__device__ __forceinline__ uint32_t smem_u32(const void* p) {
    uint32_t a;
    asm("{ .reg .u64 t; cvta.to.shared.u64 t, %1; cvt.u32.u64 %0, t; }" : "=r"(a) : "l"(p));
    return a;
}
__device__ __forceinline__ void cp_async16(uint32_t dst, const void* src) {
    asm volatile("cp.async.cg.shared.global [%0], [%1], 16;" :: "r"(dst), "l"(src));
}
__device__ __forceinline__ void ldsm4(uint32_t& r0, uint32_t& r1, uint32_t& r2, uint32_t& r3, uint32_t a) {
    asm volatile("ldmatrix.sync.aligned.m8n8.x4.shared.b16 {%0,%1,%2,%3}, [%4];"
                 : "=r"(r0), "=r"(r1), "=r"(r2), "=r"(r3) : "r"(a));
}
__device__ __forceinline__ void ldsm2(uint32_t& r0, uint32_t& r1, uint32_t a) {
    asm volatile("ldmatrix.sync.aligned.m8n8.x2.shared.b16 {%0,%1}, [%2];"
                 : "=r"(r0), "=r"(r1) : "r"(a));
}
__device__ __forceinline__ void mma16816(float* d, const uint32_t* a, uint32_t b0, uint32_t b1) {
    asm volatile("mma.sync.aligned.m16n8k16.row.col.f32.f16.f16.f32 "
                 "{%0,%1,%2,%3}, {%4,%5,%6,%7}, {%8,%9}, {%0,%1,%2,%3};"
                 : "+f"(d[0]), "+f"(d[1]), "+f"(d[2]), "+f"(d[3])
                 : "r"(a[0]), "r"(a[1]), "r"(a[2]), "r"(a[3]), "r"(b0), "r"(b1));
}
// P pair for 2 j's: adj * (u>=inva ? a*u : b*v), packed f16x2
__device__ __forceinline__ uint32_t frag(int2 w, __half2 u2, __half2 v2,
                                         __half2 a2, __half2 b2, __half2 iv2) {
    __half2 sel = __hge2(u2, iv2);
    __half2 au = __hmul2(a2, u2);
    __half2 bv = __hmul2(b2, v2);
    __half2 val = __hfma2(sel, __hsub2(au, bv), bv);
    uint32_t m = (uint32_t)w.x * 0x3C00u + (uint32_t)w.y * 0x3C000000u;
    __half2 res = __hmul2(val, *reinterpret_cast<__half2*>(&m));
    return *reinterpret_cast<uint32_t*>(&res);
}

// ============ Kernel 1: h = input@W fused with all prep (smem W, MLP=8) ============
__global__ void __launch_bounds__(256) k_prep(const float* __restrict__ inp,
                                              const float* __restrict__ W,
                                              const float* __restrict__ av) {
    extern __shared__ float Ws[];   // 64KB
    const int tid = threadIdx.x;
    // stage W: 16384 floats = 4096 float4, 16 per thread
#pragma unroll
    for (int i = tid; i < (EMBD * NHID) / 4; i += 256)
        reinterpret_cast<float4*>(Ws)[i] = __ldg(reinterpret_cast<const float4*>(W) + i);
    __syncthreads();

    const int j = blockIdx.x * 32 + (tid >> 3);
    const int c0 = (tid & 7) * 8;
    float acc[8];
#pragma unroll
    for (int i = 0; i < 8; i++) acc[i] = 0.f;
    const float* ir = inp + (size_t)j * EMBD;

#pragma unroll
    for (int k0 = 0; k0 < EMBD; k0 += 32) {
        float4 xs[8];
#pragma unroll
        for (int i = 0; i < 8; i++)
            xs[i] = __ldg(reinterpret_cast<const float4*>(ir + k0 + i * 4));
#pragma unroll
        for (int i = 0; i < 8; i++) {
#pragma unroll
            for (int kk = 0; kk < 4; kk++) {
                float xv = (&xs[i].x)[kk];
                const float* wr = Ws + (k0 + i * 4 + kk) * NHID + c0;
                float4 w0 = *reinterpret_cast<const float4*>(wr);
                float4 w1 = *reinterpret_cast<const float4*>(wr + 4);
                acc[0] += xv * w0.x; acc[1] += xv * w0.y; acc[2] += xv * w0.z; acc[3] += xv * w0.w;
                acc[4] += xv * w1.x; acc[5] += xv * w1.y; acc[6] += xv * w1.z; acc[7] += xv * w1.w;
            }
        }
    }
    // s,t via 8-lane reduction
    float s = 0.f, t = 0.f;
#pragma unroll
    for (int k = 0; k < 8; k++) {
        s += acc[k] * __ldg(av + c0 + k);
        t += acc[k] * __ldg(av + 64 + c0 + k);
    }
#pragma unroll
    for (int o = 1; o < 8; o <<= 1) {
        s += __shfl_xor_sync(0xFFFFFFFFu, s, o);
        t += __shfl_xor_sync(0xFFFFFFFFu, t, o);
    }
    // B matrix columns (transposed: [c][j])
#pragma unroll
    for (int k = 0; k < 8; k++)
        g_Bm[(size_t)(c0 + k) * NN + j] = __float2half(acc[k]);
    if ((tid & 7) == 0) {
        g_u[j] = __float2half(expf(t));
        g_v[j] = __float2half(expf(ALPHA * t));
        g_af[j] = expf(s);
        g_bf[j] = expf(ALPHA * s);
        g_iv[j] = expf(-s);
        g_Bm[(size_t)64 * NN + j] = __float2half(1.f);
#pragma unroll
        for (int c = 65; c < NB; c++) g_Bm[(size_t)c * NN + j] = __half(0.f);
    }
}

// ============ Kernel 2: single masked GEMM via mma.sync ============
__device__ __forceinline__ void issue_chunk(uint32_t sb, const int* __restrict__ adj,
                                            int I0, int jb, int st, int tid) {
    const uint32_t stage = sb + STAGE0 + st * STAGE_SZ;
#pragma unroll
    for (int it = 0; it < 8; it++) {
        int u = tid + it * 256;
        int row = u >> 4, ku = u & 15;
        cp_async16(stage + (uint32_t)(row * 256 + ((ku * 16) ^ ((row & 7) << 4))),
                   adj + (size_t)(I0 + row) * NN + jb + ku * 4);
    }
    const uint32_t bst = stage + ADJ_SZ;
#pragma unroll
    for (int it = 0; it < 3; it++) {
        int v = tid + it * 256;
        if (v < 576) {
            int c = v >> 3, seg = v & 7;
            cp_async16(bst + (uint32_t)(c * 128 + ((seg * 16) ^ ((c & 7) << 4))),
                       g_Bm + (size_t)c * NN + jb + seg * 8);
        }
    }
    asm volatile("cp.async.commit_group;" ::: "memory");
}

__global__ void __launch_bounds__(256, 1) k_attn(const int* __restrict__ adj) {
    extern __shared__ char smem[];
    const uint32_t sb = smem_u32(smem);
    const int tid = threadIdx.x;
    const int wid = tid >> 5, lane = tid & 31;
    const int r = lane >> 2, cL = lane & 3;
    const int rloc = wid * 16 + r;
    const int I0 = blockIdx.x * MROWS;
    const int jh = blockIdx.y;
    const int jbase0 = jh * JHALF;

    issue_chunk(sb, adj, I0, jbase0, 0, tid);
    issue_chunk(sb, adj, I0, jbase0 + KC, 1, tid);

    __half* u_sh = reinterpret_cast<__half*>(smem + U_OFF);
    __half* v_sh = reinterpret_cast<__half*>(smem + V_OFF);
#pragma unroll
    for (int i = tid; i < JHALF / 8; i += 256) {
        reinterpret_cast<float4*>(u_sh)[i] = reinterpret_cast<const float4*>(g_u + jbase0)[i];
        reinterpret_cast<float4*>(v_sh)[i] = reinterpret_cast<const float4*>(g_v + jbase0)[i];
    }

    const int i0 = I0 + rloc, i1 = i0 + 8;
    const __half2 a20 = __float2half2_rn(g_af[i0]), b20 = __float2half2_rn(g_bf[i0]);
    const __half2 iv0 = __float2half2_rn(g_iv[i0]);
    const __half2 a21 = __float2half2_rn(g_af[i1]), b21 = __float2half2_rn(g_bf[i1]);
    const __half2 iv1 = __float2half2_rn(g_iv[i1]);

    const uint32_t swzA = (uint32_t)(r << 4);
    const uint32_t swzB = (uint32_t)((lane & 7) << 4);
    const uint32_t kaddB = (uint32_t)(((lane >> 3) & 1) * 16);
    uint32_t rb[5];
#pragma unroll
    for (int g = 0; g < 4; g++)
        rb[g] = (uint32_t)(((2 * g + ((lane >> 4) & 1)) * 8 + (lane & 7)) * 128);
    rb[4] = (uint32_t)((64 + (lane & 7)) * 128);

    float acc[9][4];
#pragma unroll
    for (int nt = 0; nt < 9; nt++)
#pragma unroll
        for (int k = 0; k < 4; k++) acc[nt][k] = 0.f;

    for (int q = 0; q < NCHUNK; q++) {
        if (q + 2 < NCHUNK)
            issue_chunk(sb, adj, I0, jbase0 + (q + 2) * KC, (q + 2) & 3, tid);
        if (q < NCHUNK - 2)      asm volatile("cp.async.wait_group 2;" ::: "memory");
        else if (q == NCHUNK - 2) asm volatile("cp.async.wait_group 1;" ::: "memory");
        else                      asm volatile("cp.async.wait_group 0;" ::: "memory");
        __syncthreads();

        const char* adjp = smem + STAGE0 + (q & 3) * STAGE_SZ;
        const uint32_t bstB = sb + STAGE0 + (q & 3) * STAGE_SZ + ADJ_SZ;
        const __half* uq = u_sh + q * KC;
        const __half* vq = v_sh + q * KC;

#pragma unroll
        for (int ksi = 0; ksi < 4; ksi++) {
            const int ks = ksi * 16;
            __half2 u2lo = *reinterpret_cast<const __half2*>(uq + ks + 2 * cL);
            __half2 v2lo = *reinterpret_cast<const __half2*>(vq + ks + 2 * cL);
            __half2 u2hi = *reinterpret_cast<const __half2*>(uq + ks + 8 + 2 * cL);
            __half2 v2hi = *reinterpret_cast<const __half2*>(vq + ks + 8 + 2 * cL);
            uint32_t ka = (uint32_t)(ks * 4 + cL * 8);
            int2 w00 = *reinterpret_cast<const int2*>(adjp + rloc * 256 + (ka ^ swzA));
            int2 w10 = *reinterpret_cast<const int2*>(adjp + (rloc + 8) * 256 + (ka ^ swzA));
            int2 w01 = *reinterpret_cast<const int2*>(adjp + rloc * 256 + ((ka + 32) ^ swzA));
            int2 w11 = *reinterpret_cast<const int2*>(adjp + (rloc + 8) * 256 + ((ka + 32) ^ swzA));

            uint32_t A[4];
            A[0] = frag(w00, u2lo, v2lo, a20, b20, iv0);
            A[1] = frag(w10, u2lo, v2lo, a21, b21, iv1);
            A[2] = frag(w01, u2hi, v2hi, a20, b20, iv0);
            A[3] = frag(w11, u2hi, v2hi, a21, b21, iv1);

            const uint32_t inner = ((uint32_t)(ks * 2) + kaddB) ^ swzB;
#pragma unroll
            for (int g = 0; g < 4; g++) {
                uint32_t b0, b1, b2, b3;
                ldsm4(b0, b1, b2, b3, bstB + rb[g] + inner);
                mma16816(acc[2 * g], A, b0, b1);
                mma16816(acc[2 * g + 1], A, b2, b3);
            }
            {
                uint32_t b0, b1;
                ldsm2(b0, b1, bstB + rb[4] + inner);
                mma16816(acc[8], A, b0, b1);
            }
        }
    }

    float* p0 = g_part + ((size_t)jh * NN + i0) * NB;
    float* p1 = g_part + ((size_t)jh * NN + i1) * NB;
#pragma unroll
    for (int nt = 0; nt < 9; nt++) {
        const int n = nt * 8 + 2 * cL;
        *reinterpret_cast<float2*>(p0 + n) = make_float2(acc[nt][0], acc[nt][1]);
        *reinterpret_cast<float2*>(p1 + n) = make_float2(acc[nt][2], acc[nt][3]);
    }
}

// ============ Kernel 3: combine halves, divide (2 elems/thread) ============
__global__ void __launch_bounds__(256) k_combine(float* __restrict__ out) {
    int e = blockIdx.x * 256 + threadIdx.x;     // pair index
    int i = e >> 5, c = (e & 31) * 2;
    const float* p0 = g_part + (size_t)i * NB;
    const float* p1 = g_part + (size_t)(NN + i) * NB;
    float rden = 1.f / (p0[64] + p1[64]);
    float2 x0 = *reinterpret_cast<const float2*>(p0 + c);
    float2 x1 = *reinterpret_cast<const float2*>(p1 + c);
    *reinterpret_cast<float2*>(out + (size_t)i * NHID + c) =
        make_float2((x0.x + x1.x) * rden, (x0.y + x1.y) * rden);
}

// ============ launcher ============
extern "C" void kernel_launch(void* const* d_in, const int* in_sizes, int n_in,
                              void* d_out, int out_size) {
    const float* inp = (const float*)d_in[0];
    const int* adj   = (const int*)d_in[1];
    const float* W   = (const float*)d_in[2];
    const float* av  = (const float*)d_in[3];
    float* out = (float*)d_out;
    (void)in_sizes; (void)n_in; (void)out_size;

    cudaFuncSetAttribute(k_prep, cudaFuncAttributeMaxDynamicSharedMemorySize, SMEM1_TOTAL);
    cudaFuncSetAttribute(k_attn, cudaFuncAttributeMaxDynamicSharedMemorySize, SMEM3_TOTAL);

    k_prep<<<NN / 32, 256, SMEM1_TOTAL>>>(inp, W, av);
    dim3 g3(NN / MROWS, JSPLIT);
    k_attn<<<g3, 256, SMEM3_TOTAL>>>(adj);
    k_combine<<<(NN * NHID / 2) / 256, 256>>>(out);
}

// round 6
// speedup vs baseline: 2.0214x; 1.2298x over previous
#include <cuda_runtime.h>
#include <cuda_fp16.h>
#include <cstdint>
#include <cstddef>

#define NN 8192
#define EMBD 256
#define NHID 64
#define ALPHA 0.2f

#define MROWS 128
#define KC 64
#define NB 72
#define JSPLIT 2
#define JHALF (NN / JSPLIT)
#define NCHUNK (JHALF / KC)   // 64

// smem layout (k_attn): u/v tables then 4 pipeline stages
#define U_OFF 0
#define V_OFF 8192
#define STAGE0 16384
#define ADJ_SZ 32768                       // 128 rows x 256B
#define B_SZ 9216                          // 72 rows x 128B
#define STAGE_SZ (ADJ_SZ + B_SZ)           // 41984
#define NSTAGE 4
#define SMEM3_TOTAL (STAGE0 + NSTAGE * STAGE_SZ)   // 184320

#define SMEM1_TOTAL (EMBD * NHID * 4)      // 64KB W staging

// ---------------- device scratch ----------------
__device__ __half g_Bm[NB * NN];            // [c][j]: h cols (c<64), ones (64), pad 0
__device__ __half g_u[NN], g_v[NN];         // exp(t_j), exp(a*t_j)
__device__ float g_af[NN], g_bf[NN], g_iv[NN];  // exp(s), exp(a*s), exp(-s)
__device__ float g_part[JSPLIT * NN * NB];  // numer 0..63, denom 64

// ---------------- helpers ----------------
__device__ __forceinline__ uint32_t smem_u32(const void* p) {
    uint32_t a;
    asm("{ .reg .u64 t; cvta.to.shared.u64 t, %1; cvt.u32.u64 %0, t; }" : "=r"(a) : "l"(p));
    return a;
}
__device__ __forceinline__ void cp_async16(uint32_t dst, const void* src) {
    asm volatile("cp.async.cg.shared.global [%0], [%1], 16;" :: "r"(dst), "l"(src));
}
__device__ __forceinline__ void ldsm4(uint32_t& r0, uint32_t& r1, uint32_t& r2, uint32_t& r3, uint32_t a) {
    asm volatile("ldmatrix.sync.aligned.m8n8.x4.shared.b16 {%0,%1,%2,%3}, [%4];"
                 : "=r"(r0), "=r"(r1), "=r"(r2), "=r"(r3) : "r"(a));
}
__device__ __forceinline__ void ldsm2(uint32_t& r0, uint32_t& r1, uint32_t a) {
    asm volatile("ldmatrix.sync.aligned.m8n8.x2.shared.b16 {%0,%1}, [%2];"
                 : "=r"(r0), "=r"(r1) : "r"(a));
}
__device__ __forceinline__ void mma16816(float* d, const uint32_t* a, uint32_t b0, uint32_t b1) {
    asm volatile("mma.sync.aligned.m16n8k16.row.col.f32.f16.f16.f32 "
                 "{%0,%1,%2,%3}, {%4,%5,%6,%7}, {%8,%9}, {%0,%1,%2,%3};"
                 : "+f"(d[0]), "+f"(d[1]), "+f"(d[2]), "+f"(d[3])
                 : "r"(a[0]), "r"(a[1]), "r"(a[2]), "r"(a[3]), "r"(b0), "r"(b1));
}
// P pair for 2 j's: adj * (u>=inva ? a*u : b*v), packed f16x2
__device__ __forceinline__ uint32_t frag(int2 w, __half2 u2, __half2 v2,
                                         __half2 a2, __half2 b2, __half2 iv2) {
    __half2 sel = __hge2(u2, iv2);
    __half2 au = __hmul2(a2, u2);
    __half2 bv = __hmul2(b2, v2);
    __half2 val = __hfma2(sel, __hsub2(au, bv), bv);
    uint32_t m = (uint32_t)w.x * 0x3C00u + (uint32_t)w.y * 0x3C000000u;
    __half2 res = __hmul2(val, *reinterpret_cast<__half2*>(&m));
    return *reinterpret_cast<uint32_t*>(&res);
}

// ===== Kernel 1: h = input@W + prep, 2-way j-coarsened (smem W amortized) =====
__global__ void __launch_bounds__(256) k_prep(const float* __restrict__ inp,
                                              const float* __restrict__ W,
                                              const float* __restrict__ av) {
    extern __shared__ float Ws[];   // 64KB
    const int tid = threadIdx.x;
#pragma unroll
    for (int i = tid; i < (EMBD * NHID) / 4; i += 256)
        reinterpret_cast<float4*>(Ws)[i] = __ldg(reinterpret_cast<const float4*>(W) + i);
    __syncthreads();

    const int g = tid >> 3;                     // 32 row-groups
    const int j0 = blockIdx.x * 64 + g * 2;     // 2 rows per thread
    const int c0 = (tid & 7) * 8;
    float acc0[8], acc1[8];
#pragma unroll
    for (int i = 0; i < 8; i++) { acc0[i] = 0.f; acc1[i] = 0.f; }
    const float* ir0 = inp + (size_t)j0 * EMBD;
    const float* ir1 = ir0 + EMBD;

#pragma unroll
    for (int k0 = 0; k0 < EMBD; k0 += 16) {
        float4 x0[4], x1[4];
#pragma unroll
        for (int i = 0; i < 4; i++) {
            x0[i] = __ldg(reinterpret_cast<const float4*>(ir0 + k0 + i * 4));
            x1[i] = __ldg(reinterpret_cast<const float4*>(ir1 + k0 + i * 4));
        }
#pragma unroll
        for (int i = 0; i < 4; i++) {
#pragma unroll
            for (int kk = 0; kk < 4; kk++) {
                const float* wr = Ws + (k0 + i * 4 + kk) * NHID + c0;
                float4 w0 = *reinterpret_cast<const float4*>(wr);
                float4 w1 = *reinterpret_cast<const float4*>(wr + 4);
                float xa = (&x0[i].x)[kk], xb = (&x1[i].x)[kk];
                acc0[0] += xa * w0.x; acc0[1] += xa * w0.y; acc0[2] += xa * w0.z; acc0[3] += xa * w0.w;
                acc0[4] += xa * w1.x; acc0[5] += xa * w1.y; acc0[6] += xa * w1.z; acc0[7] += xa * w1.w;
                acc1[0] += xb * w0.x; acc1[1] += xb * w0.y; acc1[2] += xb * w0.z; acc1[3] += xb * w0.w;
                acc1[4] += xb * w1.x; acc1[5] += xb * w1.y; acc1[6] += xb * w1.z; acc1[7] += xb * w1.w;
            }
        }
    }
    // s,t via 8-lane reductions (per row)
    float s0 = 0.f, t0 = 0.f, s1 = 0.f, t1 = 0.f;
#pragma unroll
    for (int k = 0; k < 8; k++) {
        float wa = __ldg(av + c0 + k), wb = __ldg(av + 64 + c0 + k);
        s0 += acc0[k] * wa; t0 += acc0[k] * wb;
        s1 += acc1[k] * wa; t1 += acc1[k] * wb;
    }
#pragma unroll
    for (int o = 1; o < 8; o <<= 1) {
        s0 += __shfl_xor_sync(0xFFFFFFFFu, s0, o);
        t0 += __shfl_xor_sync(0xFFFFFFFFu, t0, o);
        s1 += __shfl_xor_sync(0xFFFFFFFFu, s1, o);
        t1 += __shfl_xor_sync(0xFFFFFFFFu, t1, o);
    }
    // B matrix columns (transposed: [c][j]) — adjacent j pair -> 4B store
#pragma unroll
    for (int k = 0; k < 8; k++) {
        __half2 hp = __floats2half2_rn(acc0[k], acc1[k]);
        *reinterpret_cast<__half2*>(&g_Bm[(size_t)(c0 + k) * NN + j0]) = hp;
    }
    if ((tid & 7) == 0) {
        *reinterpret_cast<__half2*>(&g_u[j0]) = __floats2half2_rn(expf(t0), expf(t1));
        *reinterpret_cast<__half2*>(&g_v[j0]) = __floats2half2_rn(expf(ALPHA * t0), expf(ALPHA * t1));
        g_af[j0] = expf(s0);        g_af[j0 + 1] = expf(s1);
        g_bf[j0] = expf(ALPHA * s0); g_bf[j0 + 1] = expf(ALPHA * s1);
        g_iv[j0] = expf(-s0);        g_iv[j0 + 1] = expf(-s1);
        *reinterpret_cast<__half2*>(&g_Bm[(size_t)64 * NN + j0]) = __floats2half2_rn(1.f, 1.f);
#pragma unroll
        for (int c = 65; c < NB; c++)
            *reinterpret_cast<__half2*>(&g_Bm[(size_t)c * NN + j0]) = __floats2half2_rn(0.f, 0.f);
    }
}

// ============ Kernel 2: single masked GEMM via mma.sync ============
__device__ __forceinline__ void issue_chunk(uint32_t sb, const int* __restrict__ adj,
                                            int I0, int jb, int st, int tid) {
    const uint32_t stage = sb + STAGE0 + st * STAGE_SZ;
#pragma unroll
    for (int it = 0; it < 8; it++) {
        int u = tid + it * 256;
        int row = u >> 4, ku = u & 15;
        cp_async16(stage + (uint32_t)(row * 256 + ((ku * 16) ^ ((row & 7) << 4))),
                   adj + (size_t)(I0 + row) * NN + jb + ku * 4);
    }
    const uint32_t bst = stage + ADJ_SZ;
#pragma unroll
    for (int it = 0; it < 3; it++) {
        int v = tid + it * 256;
        if (v < 576) {
            int c = v >> 3, seg = v & 7;
            cp_async16(bst + (uint32_t)(c * 128 + ((seg * 16) ^ ((c & 7) << 4))),
                       g_Bm + (size_t)c * NN + jb + seg * 8);
        }
    }
    asm volatile("cp.async.commit_group;" ::: "memory");
}

__global__ void __launch_bounds__(256, 1) k_attn(const int* __restrict__ adj) {
    extern __shared__ char smem[];
    const uint32_t sb = smem_u32(smem);
    const int tid = threadIdx.x;
    const int wid = tid >> 5, lane = tid & 31;
    const int r = lane >> 2, cL = lane & 3;
    const int rloc = wid * 16 + r;
    const int I0 = blockIdx.x * MROWS;
    const int jh = blockIdx.y;
    const int jbase0 = jh * JHALF;

    issue_chunk(sb, adj, I0, jbase0, 0, tid);
    issue_chunk(sb, adj, I0, jbase0 + KC, 1, tid);

    __half* u_sh = reinterpret_cast<__half*>(smem + U_OFF);
    __half* v_sh = reinterpret_cast<__half*>(smem + V_OFF);
#pragma unroll
    for (int i = tid; i < JHALF / 8; i += 256) {
        reinterpret_cast<float4*>(u_sh)[i] = reinterpret_cast<const float4*>(g_u + jbase0)[i];
        reinterpret_cast<float4*>(v_sh)[i] = reinterpret_cast<const float4*>(g_v + jbase0)[i];
    }

    const int i0 = I0 + rloc, i1 = i0 + 8;
    const __half2 a20 = __float2half2_rn(g_af[i0]), b20 = __float2half2_rn(g_bf[i0]);
    const __half2 iv0 = __float2half2_rn(g_iv[i0]);
    const __half2 a21 = __float2half2_rn(g_af[i1]), b21 = __float2half2_rn(g_bf[i1]);
    const __half2 iv1 = __float2half2_rn(g_iv[i1]);

    const uint32_t swzA = (uint32_t)(r << 4);
    const uint32_t swzB = (uint32_t)((lane & 7) << 4);
    const uint32_t kaddB = (uint32_t)(((lane >> 3) & 1) * 16);
    uint32_t rb[5];
#pragma unroll
    for (int g = 0; g < 4; g++)
        rb[g] = (uint32_t)(((2 * g + ((lane >> 4) & 1)) * 8 + (lane & 7)) * 128);
    rb[4] = (uint32_t)((64 + (lane & 7)) * 128);

    float acc[9][4];
#pragma unroll
    for (int nt = 0; nt < 9; nt++)
#pragma unroll
        for (int k = 0; k < 4; k++) acc[nt][k] = 0.f;

    for (int q = 0; q < NCHUNK; q++) {
        if (q + 2 < NCHUNK)
            issue_chunk(sb, adj, I0, jbase0 + (q + 2) * KC, (q + 2) & 3, tid);
        if (q < NCHUNK - 2)      asm volatile("cp.async.wait_group 2;" ::: "memory");
        else if (q == NCHUNK - 2) asm volatile("cp.async.wait_group 1;" ::: "memory");
        else                      asm volatile("cp.async.wait_group 0;" ::: "memory");
        __syncthreads();

        const char* adjp = smem + STAGE0 + (q & 3) * STAGE_SZ;
        const uint32_t bstB = sb + STAGE0 + (q & 3) * STAGE_SZ + ADJ_SZ;
        const __half* uq = u_sh + q * KC;
        const __half* vq = v_sh + q * KC;

#pragma unroll
        for (int ksi = 0; ksi < 4; ksi++) {
            const int ks = ksi * 16;
            __half2 u2lo = *reinterpret_cast<const __half2*>(uq + ks + 2 * cL);
            __half2 v2lo = *reinterpret_cast<const __half2*>(vq + ks + 2 * cL);
            __half2 u2hi = *reinterpret_cast<const __half2*>(uq + ks + 8 + 2 * cL);
            __half2 v2hi = *reinterpret_cast<const __half2*>(vq + ks + 8 + 2 * cL);
            uint32_t ka = (uint32_t)(ks * 4 + cL * 8);
            int2 w00 = *reinterpret_cast<const int2*>(adjp + rloc * 256 + (ka ^ swzA));
            int2 w10 = *reinterpret_cast<const int2*>(adjp + (rloc + 8) * 256 + (ka ^ swzA));
            int2 w01 = *reinterpret_cast<const int2*>(adjp + rloc * 256 + ((ka + 32) ^ swzA));
            int2 w11 = *reinterpret_cast<const int2*>(adjp + (rloc + 8) * 256 + ((ka + 32) ^ swzA));

            uint32_t A[4];
            A[0] = frag(w00, u2lo, v2lo, a20, b20, iv0);
            A[1] = frag(w10, u2lo, v2lo, a21, b21, iv1);
            A[2] = frag(w01, u2hi, v2hi, a20, b20, iv0);
            A[3] = frag(w11, u2hi, v2hi, a21, b21, iv1);

            const uint32_t inner = ((uint32_t)(ks * 2) + kaddB) ^ swzB;
#pragma unroll
            for (int g = 0; g < 4; g++) {
                uint32_t b0, b1, b2, b3;
                ldsm4(b0, b1, b2, b3, bstB + rb[g] + inner);
                mma16816(acc[2 * g], A, b0, b1);
                mma16816(acc[2 * g + 1], A, b2, b3);
            }
            {
                uint32_t b0, b1;
                ldsm2(b0, b1, bstB + rb[4] + inner);
                mma16816(acc[8], A, b0, b1);
            }
        }
    }

    float* p0 = g_part + ((size_t)jh * NN + i0) * NB;
    float* p1 = g_part + ((size_t)jh * NN + i1) * NB;
#pragma unroll
    for (int nt = 0; nt < 9; nt++) {
        const int n = nt * 8 + 2 * cL;
        *reinterpret_cast<float2*>(p0 + n) = make_float2(acc[nt][0], acc[nt][1]);
        *reinterpret_cast<float2*>(p1 + n) = make_float2(acc[nt][2], acc[nt][3]);
    }
}

// ============ Kernel 3: combine halves, divide (2 elems/thread) ============
__global__ void __launch_bounds__(256) k_combine(float* __restrict__ out) {
    int e = blockIdx.x * 256 + threadIdx.x;     // pair index
    int i = e >> 5, c = (e & 31) * 2;
    const float* p0 = g_part + (size_t)i * NB;
    const float* p1 = g_part + (size_t)(NN + i) * NB;
    float rden = 1.f / (p0[64] + p1[64]);
    float2 x0 = *reinterpret_cast<const float2*>(p0 + c);
    float2 x1 = *reinterpret_cast<const float2*>(p1 + c);
    *reinterpret_cast<float2*>(out + (size_t)i * NHID + c) =
        make_float2((x0.x + x1.x) * rden, (x0.y + x1.y) * rden);
}

// ============ launcher ============
extern "C" void kernel_launch(void* const* d_in, const int* in_sizes, int n_in,
                              void* d_out, int out_size) {
    const float* inp = (const float*)d_in[0];
    const int* adj   = (const int*)d_in[1];
    const float* W   = (const float*)d_in[2];
    const float* av  = (const float*)d_in[3];
    float* out = (float*)d_out;
    (void)in_sizes; (void)n_in; (void)out_size;

    cudaFuncSetAttribute(k_prep, cudaFuncAttributeMaxDynamicSharedMemorySize, SMEM1_TOTAL);
    cudaFuncSetAttribute(k_attn, cudaFuncAttributeMaxDynamicSharedMemorySize, SMEM3_TOTAL);

    k_prep<<<NN / 64, 256, SMEM1_TOTAL>>>(inp, W, av);
    dim3 g3(NN / MROWS, JSPLIT);
    k_attn<<<g3, 256, SMEM3_TOTAL>>>(adj);
    k_combine<<<(NN * NHID / 2) / 256, 256>>>(out);
}

// round 7
// speedup vs baseline: 2.4045x; 1.1896x over previous
#include <cuda_runtime.h>
#include <cuda_fp16.h>
#include <cstdint>
#include <cstddef>

#define NN 8192
#define EMBD 256
#define NHID 64
#define ALPHA 0.2f

#define MROWS 128
#define KC 64
#define NB 72
#define JSPLIT 4
#define JQ (NN / JSPLIT)          // 2048
#define NCHUNK (JQ / KC)          // 32

// k_attn smem: u/v tables (per j-quarter) then 2 pipeline stages
#define U_OFF 0
#define V_OFF 4096
#define STAGE0 8192
#define ADJ_SZ 32768                       // 128 rows x 256B
#define B_SZ 9216                          // 72 rows x 128B
#define STAGE_SZ (ADJ_SZ + B_SZ)           // 41984
#define NSTAGE 2
#define SMEM3_TOTAL (STAGE0 + NSTAGE * STAGE_SZ)   // 92160

#define SMEM1_TOTAL (EMBD * NHID * 4)      // 64KB W staging

// ---------------- device scratch ----------------
__device__ __half g_Bm[NB * NN];            // [c][j]: h cols (c<64), ones (64), pad 0
__device__ __half g_u[NN], g_v[NN];         // exp(t_j), exp(a*t_j)
__device__ float g_af[NN], g_bf[NN], g_iv[NN];  // exp(s), exp(a*s), exp(-s)
__device__ float g_part[JSPLIT * NN * NB];  // numer 0..63, denom 64

// ---------------- helpers ----------------
__device__ __forceinline__ uint32_t smem_u32(const void* p) {
    uint32_t a;
    asm("{ .reg .u64 t; cvta.to.shared.u64 t, %1; cvt.u32.u64 %0, t; }" : "=r"(a) : "l"(p));
    return a;
}
__device__ __forceinline__ void cp_async16(uint32_t dst, const void* src) {
    asm volatile("cp.async.cg.shared.global [%0], [%1], 16;" :: "r"(dst), "l"(src));
}
__device__ __forceinline__ void ldsm4(uint32_t& r0, uint32_t& r1, uint32_t& r2, uint32_t& r3, uint32_t a) {
    asm volatile("ldmatrix.sync.aligned.m8n8.x4.shared.b16 {%0,%1,%2,%3}, [%4];"
                 : "=r"(r0), "=r"(r1), "=r"(r2), "=r"(r3) : "r"(a));
}
__device__ __forceinline__ void ldsm2(uint32_t& r0, uint32_t& r1, uint32_t a) {
    asm volatile("ldmatrix.sync.aligned.m8n8.x2.shared.b16 {%0,%1}, [%2];"
                 : "=r"(r0), "=r"(r1) : "r"(a));
}
__device__ __forceinline__ void mma16816(float* d, const uint32_t* a, uint32_t b0, uint32_t b1) {
    asm volatile("mma.sync.aligned.m16n8k16.row.col.f32.f16.f16.f32 "
                 "{%0,%1,%2,%3}, {%4,%5,%6,%7}, {%8,%9}, {%0,%1,%2,%3};"
                 : "+f"(d[0]), "+f"(d[1]), "+f"(d[2]), "+f"(d[3])
                 : "r"(a[0]), "r"(a[1]), "r"(a[2]), "r"(a[3]), "r"(b0), "r"(b1));
}
// P pair for 2 j's: adj * (u>=inva ? a*u : b*v), packed f16x2
__device__ __forceinline__ uint32_t frag(int2 w, __half2 u2, __half2 v2,
                                         __half2 a2, __half2 b2, __half2 iv2) {
    __half2 sel = __hge2(u2, iv2);
    __half2 au = __hmul2(a2, u2);
    __half2 bv = __hmul2(b2, v2);
    __half2 val = __hfma2(sel, __hsub2(au, bv), bv);
    uint32_t m = (uint32_t)w.x * 0x3C00u + (uint32_t)w.y * 0x3C000000u;
    __half2 res = __hmul2(val, *reinterpret_cast<__half2*>(&m));
    return *reinterpret_cast<uint32_t*>(&res);
}

// ===== Kernel 1: h = input@W + prep, 4 rows x 4 cols per thread =====
__global__ void __launch_bounds__(256) k_prep(const float* __restrict__ inp,
                                              const float* __restrict__ W,
                                              const float* __restrict__ av) {
    extern __shared__ float Ws[];   // 64KB
    const int tid = threadIdx.x;
#pragma unroll
    for (int i = tid; i < (EMBD * NHID) / 4; i += 256)
        reinterpret_cast<float4*>(Ws)[i] = __ldg(reinterpret_cast<const float4*>(W) + i);
    __syncthreads();

    const int rg = tid >> 4;                    // 16 row groups
    const int j0 = blockIdx.x * 64 + rg * 4;    // 4 rows/thread
    const int c0 = (tid & 15) * 4;              // 4 cols/thread
    float acc[4][4];
#pragma unroll
    for (int rr = 0; rr < 4; rr++)
#pragma unroll
        for (int k = 0; k < 4; k++) acc[rr][k] = 0.f;

    const float* ir = inp + (size_t)j0 * EMBD;
#pragma unroll
    for (int k0 = 0; k0 < EMBD; k0 += 8) {
        float4 xs[4][2];
#pragma unroll
        for (int rr = 0; rr < 4; rr++) {
            xs[rr][0] = __ldg(reinterpret_cast<const float4*>(ir + (size_t)rr * EMBD + k0));
            xs[rr][1] = __ldg(reinterpret_cast<const float4*>(ir + (size_t)rr * EMBD + k0 + 4));
        }
#pragma unroll
        for (int kb = 0; kb < 8; kb++) {
            float4 w = *reinterpret_cast<const float4*>(Ws + (k0 + kb) * NHID + c0);
#pragma unroll
            for (int rr = 0; rr < 4; rr++) {
                float xv = (&xs[rr][kb >> 2].x)[kb & 3];
                acc[rr][0] += xv * w.x; acc[rr][1] += xv * w.y;
                acc[rr][2] += xv * w.z; acc[rr][3] += xv * w.w;
            }
        }
    }
    // s,t per row via 16-lane reductions
    float s[4], t[4];
#pragma unroll
    for (int rr = 0; rr < 4; rr++) {
        float ss = 0.f, tt = 0.f;
#pragma unroll
        for (int k = 0; k < 4; k++) {
            ss += acc[rr][k] * __ldg(av + c0 + k);
            tt += acc[rr][k] * __ldg(av + 64 + c0 + k);
        }
#pragma unroll
        for (int o = 1; o < 16; o <<= 1) {
            ss += __shfl_xor_sync(0xFFFFFFFFu, ss, o);
            tt += __shfl_xor_sync(0xFFFFFFFFu, tt, o);
        }
        s[rr] = ss; t[rr] = tt;
    }
    // B matrix: 4x4 block transposed -> 8B stores (4 adjacent j per col)
#pragma unroll
    for (int k = 0; k < 4; k++) {
        __half2 lo = __floats2half2_rn(acc[0][k], acc[1][k]);
        __half2 hi = __floats2half2_rn(acc[2][k], acc[3][k]);
        uint2 pk = make_uint2(*reinterpret_cast<uint32_t*>(&lo), *reinterpret_cast<uint32_t*>(&hi));
        *reinterpret_cast<uint2*>(&g_Bm[(size_t)(c0 + k) * NN + j0]) = pk;
    }
    if ((tid & 15) == 0) {
        __half2 ulo = __floats2half2_rn(expf(t[0]), expf(t[1]));
        __half2 uhi = __floats2half2_rn(expf(t[2]), expf(t[3]));
        *reinterpret_cast<uint2*>(&g_u[j0]) = make_uint2(*reinterpret_cast<uint32_t*>(&ulo),
                                                         *reinterpret_cast<uint32_t*>(&uhi));
        __half2 vlo = __floats2half2_rn(expf(ALPHA * t[0]), expf(ALPHA * t[1]));
        __half2 vhi = __floats2half2_rn(expf(ALPHA * t[2]), expf(ALPHA * t[3]));
        *reinterpret_cast<uint2*>(&g_v[j0]) = make_uint2(*reinterpret_cast<uint32_t*>(&vlo),
                                                         *reinterpret_cast<uint32_t*>(&vhi));
#pragma unroll
        for (int rr = 0; rr < 4; rr++) {
            g_af[j0 + rr] = expf(s[rr]);
            g_bf[j0 + rr] = expf(ALPHA * s[rr]);
            g_iv[j0 + rr] = expf(-s[rr]);
        }
        __half2 one2 = __floats2half2_rn(1.f, 1.f);
        uint2 ones = make_uint2(*reinterpret_cast<uint32_t*>(&one2), *reinterpret_cast<uint32_t*>(&one2));
        *reinterpret_cast<uint2*>(&g_Bm[(size_t)64 * NN + j0]) = ones;
#pragma unroll
        for (int c = 65; c < NB; c++)
            *reinterpret_cast<uint2*>(&g_Bm[(size_t)c * NN + j0]) = make_uint2(0u, 0u);
    }
}

// ============ Kernel 2: masked GEMM, 4 warps x 32 rows, 2 CTAs/SM ============
__device__ __forceinline__ void issue_chunk(uint32_t sb, const int* __restrict__ adj,
                                            int I0, int jb, int st, int tid) {
    const uint32_t stage = sb + STAGE0 + st * STAGE_SZ;
#pragma unroll
    for (int it = 0; it < 16; it++) {
        int u = tid + it * 128;
        int row = u >> 4, ku = u & 15;
        cp_async16(stage + (uint32_t)(row * 256 + ((ku * 16) ^ ((row & 7) << 4))),
                   adj + (size_t)(I0 + row) * NN + jb + ku * 4);
    }
    const uint32_t bst = stage + ADJ_SZ;
#pragma unroll
    for (int it = 0; it < 5; it++) {
        int v = tid + it * 128;
        if (v < 576) {
            int c = v >> 3, seg = v & 7;
            cp_async16(bst + (uint32_t)(c * 128 + ((seg * 16) ^ ((c & 7) << 4))),
                       g_Bm + (size_t)c * NN + jb + seg * 8);
        }
    }
    asm volatile("cp.async.commit_group;" ::: "memory");
}

__global__ void __launch_bounds__(128, 2) k_attn(const int* __restrict__ adj) {
    extern __shared__ char smem[];
    const uint32_t sb = smem_u32(smem);
    const int tid = threadIdx.x;
    const int wid = tid >> 5, lane = tid & 31;
    const int r = lane >> 2, cL = lane & 3;
    const int I0 = blockIdx.x * MROWS;
    const int jh = blockIdx.y;
    const int jbase0 = jh * JQ;

    issue_chunk(sb, adj, I0, jbase0, 0, tid);
    issue_chunk(sb, adj, I0, jbase0 + KC, 1, tid);

    __half* u_sh = reinterpret_cast<__half*>(smem + U_OFF);
    __half* v_sh = reinterpret_cast<__half*>(smem + V_OFF);
#pragma unroll
    for (int i = tid; i < JQ / 8; i += 128) {
        reinterpret_cast<float4*>(u_sh)[i] = reinterpret_cast<const float4*>(g_u + jbase0)[i];
        reinterpret_cast<float4*>(v_sh)[i] = reinterpret_cast<const float4*>(g_v + jbase0)[i];
    }

    // 4 row offsets per warp: wid*32 + {0,8,16,24} + r
    const int ib = I0 + wid * 32 + r;
    __half2 a2[4], b2[4], iv2[4];
#pragma unroll
    for (int p = 0; p < 4; p++) {
        a2[p]  = __float2half2_rn(g_af[ib + p * 8]);
        b2[p]  = __float2half2_rn(g_bf[ib + p * 8]);
        iv2[p] = __float2half2_rn(g_iv[ib + p * 8]);
    }

    const uint32_t swzA = (uint32_t)(r << 4);
    const uint32_t swzB = (uint32_t)((lane & 7) << 4);
    const uint32_t kaddB = (uint32_t)(((lane >> 3) & 1) * 16);
    uint32_t rb[5];
#pragma unroll
    for (int g = 0; g < 4; g++)
        rb[g] = (uint32_t)(((2 * g + ((lane >> 4) & 1)) * 8 + (lane & 7)) * 128);
    rb[4] = (uint32_t)((64 + (lane & 7)) * 128);

    float acc[2][9][4];
#pragma unroll
    for (int rt = 0; rt < 2; rt++)
#pragma unroll
        for (int nt = 0; nt < 9; nt++)
#pragma unroll
            for (int k = 0; k < 4; k++) acc[rt][nt][k] = 0.f;

    for (int q = 0; q < NCHUNK; q++) {
        if (q < NCHUNK - 1) asm volatile("cp.async.wait_group 1;" ::: "memory");
        else                asm volatile("cp.async.wait_group 0;" ::: "memory");
        __syncthreads();

        const char* adjp = smem + STAGE0 + (q & 1) * STAGE_SZ;
        const uint32_t bstB = sb + STAGE0 + (q & 1) * STAGE_SZ + ADJ_SZ;
        const __half* uq = u_sh + q * KC;
        const __half* vq = v_sh + q * KC;
        const int rbase = wid * 32 + r;

#pragma unroll
        for (int ksi = 0; ksi < 4; ksi++) {
            const int ks = ksi * 16;
            __half2 u2lo = *reinterpret_cast<const __half2*>(uq + ks + 2 * cL);
            __half2 v2lo = *reinterpret_cast<const __half2*>(vq + ks + 2 * cL);
            __half2 u2hi = *reinterpret_cast<const __half2*>(uq + ks + 8 + 2 * cL);
            __half2 v2hi = *reinterpret_cast<const __half2*>(vq + ks + 8 + 2 * cL);
            const uint32_t ka = (uint32_t)(ks * 4 + cL * 8);
            const uint32_t inner = ((uint32_t)(ks * 2) + kaddB) ^ swzB;

            // B fragments once per warp, reused by both row tiles
            uint32_t bb[4][4], b8[2];
#pragma unroll
            for (int g = 0; g < 4; g++)
                ldsm4(bb[g][0], bb[g][1], bb[g][2], bb[g][3], bstB + rb[g] + inner);
            ldsm2(b8[0], b8[1], bstB + rb[4] + inner);

#pragma unroll
            for (int rt = 0; rt < 2; rt++) {
                const int r0 = rbase + rt * 16;
                int2 w00 = *reinterpret_cast<const int2*>(adjp + r0 * 256 + (ka ^ swzA));
                int2 w10 = *reinterpret_cast<const int2*>(adjp + (r0 + 8) * 256 + (ka ^ swzA));
                int2 w01 = *reinterpret_cast<const int2*>(adjp + r0 * 256 + ((ka + 32) ^ swzA));
                int2 w11 = *reinterpret_cast<const int2*>(adjp + (r0 + 8) * 256 + ((ka + 32) ^ swzA));

                uint32_t A[4];
                A[0] = frag(w00, u2lo, v2lo, a2[2 * rt], b2[2 * rt], iv2[2 * rt]);
                A[1] = frag(w10, u2lo, v2lo, a2[2 * rt + 1], b2[2 * rt + 1], iv2[2 * rt + 1]);
                A[2] = frag(w01, u2hi, v2hi, a2[2 * rt], b2[2 * rt], iv2[2 * rt]);
                A[3] = frag(w11, u2hi, v2hi, a2[2 * rt + 1], b2[2 * rt + 1], iv2[2 * rt + 1]);

#pragma unroll
                for (int g = 0; g < 4; g++) {
                    mma16816(acc[rt][2 * g], A, bb[g][0], bb[g][1]);
                    mma16816(acc[rt][2 * g + 1], A, bb[g][2], bb[g][3]);
                }
                mma16816(acc[rt][8], A, b8[0], b8[1]);
            }
        }
        __syncthreads();
        if (q + 2 < NCHUNK)
            issue_chunk(sb, adj, I0, jbase0 + (q + 2) * KC, q & 1, tid);
    }

    // epilogue: raw partials
#pragma unroll
    for (int rt = 0; rt < 2; rt++) {
        const int i0 = ib + rt * 16, i1 = i0 + 8;
        float* p0 = g_part + ((size_t)jh * NN + i0) * NB;
        float* p1 = g_part + ((size_t)jh * NN + i1) * NB;
#pragma unroll
        for (int nt = 0; nt < 9; nt++) {
            const int n = nt * 8 + 2 * cL;
            *reinterpret_cast<float2*>(p0 + n) = make_float2(acc[rt][nt][0], acc[rt][nt][1]);
            *reinterpret_cast<float2*>(p1 + n) = make_float2(acc[rt][nt][2], acc[rt][nt][3]);
        }
    }
}

// ============ Kernel 3: combine quarters, divide ============
__global__ void __launch_bounds__(256) k_combine(float* __restrict__ out) {
    int e = blockIdx.x * 256 + threadIdx.x;     // pair index
    int i = e >> 5, c = (e & 31) * 2;
    float den = 0.f;
    float2 num = make_float2(0.f, 0.f);
#pragma unroll
    for (int jh = 0; jh < JSPLIT; jh++) {
        const float* p = g_part + ((size_t)jh * NN + i) * NB;
        float2 x = *reinterpret_cast<const float2*>(p + c);
        num.x += x.x; num.y += x.y;
        den += p[64];
    }
    float rden = 1.f / den;
    *reinterpret_cast<float2*>(out + (size_t)i * NHID + c) =
        make_float2(num.x * rden, num.y * rden);
}

// ============ launcher ============
extern "C" void kernel_launch(void* const* d_in, const int* in_sizes, int n_in,
                              void* d_out, int out_size) {
    const float* inp = (const float*)d_in[0];
    const int* adj   = (const int*)d_in[1];
    const float* W   = (const float*)d_in[2];
    const float* av  = (const float*)d_in[3];
    float* out = (float*)d_out;
    (void)in_sizes; (void)n_in; (void)out_size;

    cudaFuncSetAttribute(k_prep, cudaFuncAttributeMaxDynamicSharedMemorySize, SMEM1_TOTAL);
    cudaFuncSetAttribute(k_attn, cudaFuncAttributeMaxDynamicSharedMemorySize, SMEM3_TOTAL);

    k_prep<<<NN / 64, 256, SMEM1_TOTAL>>>(inp, W, av);
    dim3 g3(NN / MROWS, JSPLIT);
    k_attn<<<g3, 128, SMEM3_TOTAL>>>(adj);
    k_combine<<<(NN * NHID / 2) / 256, 256>>>(out);
}